// round 9
// baseline (speedup 1.0000x reference)
#include <cuda_runtime.h>
#include <cuda_bf16.h>
#include <cuda_fp16.h>

// CasamentoMult on GB300 — half2 MUFU: ex2.approx.f16x2 evaluates TWO
// Gaussians per MUFU instruction (2.5 MUFU/element instead of 5).
// sigma = 1/sqrt(2*pi) => log_sqrt_pi == 0; pair term = exp(-pi*diff^2)
//   = 2^(NSC2*diff^2), NSC2 = -pi*log2(e).  Collapsed form:
//  total = NE + sum_k [ 0.5*(gy+gd-c1-c2) - s ]
//             + 0.5*e(d[0]-y[0]) - 0.5*e(d[NE]-y[NE]),   NE = N-2.

#define NBLK 1184          // 148 SMs * 8
#define NTHR 256

__device__ float    g_partials[NBLK];
__device__ unsigned g_ticket = 0;

#define SC    2.1289340388624523f   // sqrt(pi*log2(e))  (scalar tail path)
#define NSC2f -4.532360141827194f   // -pi*log2(e)

// ---- f32x2 helpers (double containers; FP64 pipe never used) ----
__device__ __forceinline__ double pk2(float lo, float hi) {
    double r; asm("mov.b64 %0, {%1, %2};" : "=d"(r) : "f"(lo), "f"(hi)); return r;
}
__device__ __forceinline__ float lo2(double v) {
    return __uint_as_float((unsigned)__double2loint(v));
}
__device__ __forceinline__ float hi2(double v) {
    return __uint_as_float((unsigned)__double2hiint(v));
}
__device__ __forceinline__ double sub2(double a, double b) {   // a - b
    double r; asm("sub.rn.f32x2 %0, %1, %2;" : "=d"(r) : "d"(a), "d"(b)); return r;
}
__device__ __forceinline__ double mul2(double a, double b) {
    double r; asm("mul.rn.f32x2 %0, %1, %2;" : "=d"(r) : "d"(a), "d"(b)); return r;
}

// Two Gaussians in one MUFU: q holds 2 diffs; nv = (-pi*log2e)*q*q; half2 ex2.
__device__ __forceinline__ unsigned gpair(double q, double NS2) {
    double t  = mul2(q, NS2);
    double nv = mul2(q, t);
    float flo, fhi; unsigned h, r;
    asm("mov.b64 {%0, %1}, %2;" : "=f"(flo), "=f"(fhi) : "d"(nv));
    asm("cvt.rn.f16x2.f32 %0, %1, %2;" : "=r"(h) : "f"(fhi), "f"(flo));
    asm("ex2.approx.f16x2 %0, %1;" : "=r"(r) : "r"(h));
    return r;
}
__device__ __forceinline__ unsigned hadd2(unsigned a, unsigned b) {
    unsigned r; asm("add.rn.f16x2 %0, %1, %2;" : "=r"(r) : "r"(a), "r"(b)); return r;
}
__device__ __forceinline__ float h2sum(unsigned h) {   // lo+hi as float
    float lo, hi;
    asm("{\n\t.reg .f16 l, g;\n\tmov.b32 {l, g}, %2;\n\t"
        "cvt.f32.f16 %0, l;\n\tcvt.f32.f16 %1, g;\n\t}"
        : "=f"(lo), "=f"(hi) : "r"(h));
    return lo + hi;
}

__device__ __forceinline__ float ex2f(float a) {
    float r; asm("ex2.approx.f32 %0, %1;" : "=f"(r) : "f"(a)); return r;
}
__device__ __forceinline__ float gex_raw(float x) {   // exp(-pi*x^2), f32
    float u = x * SC;
    return ex2f(-(u * u));
}

__global__ void __launch_bounds__(NTHR)
casa_fused(const float* __restrict__ d, const float* __restrict__ y,
           int NE, int ngroups, float* __restrict__ out) {
    const double NS2 = pk2(NSC2f, NSC2f);

    float accA = 0.f;   // gy + gd   (+0.5)
    float accC = 0.f;   // c1 + c2   (-0.5)
    float accS = 0.f;   // s         (-1)
    const int stride = gridDim.x * blockDim.x;

    for (int g = blockIdx.x * blockDim.x + threadIdx.x; g < ngroups; g += stride) {
        const int base = g << 3;                   // 8 elements per group
        const float4 dA = *reinterpret_cast<const float4*>(d + base);
        const float4 dB = *reinterpret_cast<const float4*>(d + base + 4);
        const float4 yA = *reinterpret_cast<const float4*>(y + base);
        const float4 yB = *reinterpret_cast<const float4*>(y + base + 4);
        const float d8 = __ldg(d + base + 8);
        const float y8 = __ldg(y + base + 8);

        // raw even pairs (k, k+1) straight from the load quads
        double Dp[4], Yp[4];
        Dp[0] = pk2(dA.x, dA.y);  Dp[1] = pk2(dA.z, dA.w);
        Dp[2] = pk2(dB.x, dB.y);  Dp[3] = pk2(dB.z, dB.w);
        Yp[0] = pk2(yA.x, yA.y);  Yp[1] = pk2(yA.z, yA.w);
        Yp[2] = pk2(yB.x, yB.y);  Yp[3] = pk2(yB.z, yB.w);

        unsigned hA = 0u, hC = 0u, hS = 0u;        // f16x2 accumulators (0,0)

        #pragma unroll
        for (int p = 0; p < 4; p++) {
            const float dn = (p < 3) ? lo2(Dp[p + 1]) : d8;
            const float yn = (p < 3) ? lo2(Yp[p + 1]) : y8;
            const double Dq = pk2(hi2(Dp[p]), dn); // (D_{k+1}, D_{k+2})
            const double Yq = pk2(hi2(Yp[p]), yn);

            hA = hadd2(hA, gpair(sub2(Yq, Yp[p]), NS2));    // gy pair
            hA = hadd2(hA, gpair(sub2(Dq, Dp[p]), NS2));    // gd pair
            hC = hadd2(hC, gpair(sub2(Dq, Yp[p]), NS2));    // c1 pair
            hC = hadd2(hC, gpair(sub2(Dp[p], Yq), NS2));    // c2 pair
            hS = hadd2(hS, gpair(sub2(Dp[p], Yp[p]), NS2)); // s  pair
        }

        // flush per group (each half <= 8, fp16-safe)
        accA += h2sum(hA);
        accC += h2sum(hC);
        accS += h2sum(hS);
    }

    // total = 0.5*(A - C) - S
    float acc = fmaf(accA - accC, 0.5f, -accS);

    // block reduce (float)
    #pragma unroll
    for (int o = 16; o; o >>= 1) acc += __shfl_down_sync(0xffffffffu, acc, o);

    __shared__ float sh[NTHR / 32];
    __shared__ bool  s_last;
    const int lane = threadIdx.x & 31;
    const int w    = threadIdx.x >> 5;
    if (lane == 0) sh[w] = acc;
    __syncthreads();
    if (threadIdx.x == 0) {
        float v = 0.f;
        #pragma unroll
        for (int i = 0; i < NTHR / 32; i++) v += sh[i];
        g_partials[blockIdx.x] = v;
        __threadfence();
        unsigned t = atomicAdd(&g_ticket, 1u);
        s_last = (t == (unsigned)gridDim.x - 1u);
    }
    __syncthreads();
    if (!s_last) return;

    // ---- last block: deterministic double-precision finish ----
    const int tid = threadIdx.x;
    double v = 0.0;
    for (int i = tid; i < NBLK; i += NTHR)       // fixed-order per thread
        v += (double)g_partials[i];

    if (tid == 0) {
        for (int k = 8 * ngroups; k < NE; k++) { // tail (empty when NE%8==0)
            float t0 = d[k], t1 = d[k + 1], u0 = y[k], u1 = y[k + 1];
            float a = gex_raw(u1 - u0) + gex_raw(t1 - t0)
                    - gex_raw(t1 - u0) - gex_raw(t0 - u1);
            v += 0.5 * (double)a - (double)gex_raw(t0 - u0);
        }
        v += 0.5 * ((double)gex_raw(d[0] - y[0]) - (double)gex_raw(d[NE] - y[NE]));
        v += (double)NE;
    }

    #pragma unroll
    for (int o = 16; o; o >>= 1) v += __shfl_down_sync(0xffffffffu, v, o);

    __shared__ double shd[NTHR / 32];
    if (lane == 0) shd[w] = v;
    __syncthreads();
    if (tid == 0) {
        double t = 0.0;
        #pragma unroll
        for (int i = 0; i < NTHR / 32; i++) t += shd[i];
        out[0] = (float)t;
        g_ticket = 0;                  // reset for next graph replay
    }
}

extern "C" void kernel_launch(void* const* d_in, const int* in_sizes, int n_in,
                              void* d_out, int out_size) {
    const float* d = (const float*)d_in[0];
    const float* y = (const float*)d_in[1];
    float* out = (float*)d_out;

    const int n  = in_sizes[0];
    const int NE = n - 2;               // 4,000,000 for N = 4,000,002
    const int ngroups = NE / 8;         // 8 consecutive k per group

    casa_fused<<<NBLK, NTHR>>>(d, y, NE, ngroups, out);
}

// round 10
// speedup vs baseline: 1.0022x; 1.0022x over previous
#include <cuda_runtime.h>
#include <cuda_bf16.h>

// CasamentoMult on GB300 — 256-bit load experiment: the two 32B-per-thread
// streams use Blackwell LDG.E.256 (ld.global.nc.v8.f32), halving load
// requests/instructions vs 4x LDG.128.  Math identical to the R3 scalar
// version (rel_err 0).
// sigma = 1/sqrt(2*pi) => log_sqrt_pi == 0; pair term = exp(-pi*diff^2)
//   = 2^(C2*diff^2), C2 = -pi*log2(e).  Collapsed form:
//  total = NE + sum_k [ 0.5*(e(y1-y0)+e(d1-d0)-e(d1-y0)-e(d0-y1)) - e(d0-y0) ]
//             + 0.5*e(d[0]-y[0]) - 0.5*e(d[NE]-y[NE]),   NE = N-2.

#define NBLK 1184          // 148 SMs * 8
#define NTHR 256

__device__ float    g_partials[NBLK];
__device__ unsigned g_ticket = 0;

__device__ __forceinline__ float gex(float x) {
    // 2^(C2*x*x) == exp(-pi*x*x); ex2.approx flushes very negative args to 0.
    float a = (x * -4.532360141827194f) * x;   // C2 = -pi * log2(e)
    float r;
    asm("ex2.approx.f32 %0, %1;" : "=f"(r) : "f"(a));
    return r;
}

__device__ __forceinline__ void term(float& acc, float d0, float d1,
                                     float y0, float y1) {
    float gy = gex(y1 - y0);
    float gd = gex(d1 - d0);
    float c1 = gex(d1 - y0);
    float c2 = gex(d0 - y1);
    float s  = gex(d0 - y0);
    acc = fmaf((gy + gd) - (c1 + c2), 0.5f, acc) - s;
}

// 256-bit load: 8 consecutive floats in one LDG.E.256 (sm_10x).
// Requires 32-byte alignment of p (group base = 32B-aligned here).
__device__ __forceinline__ void ldg256(const float* p, float4& a, float4& b) {
    asm("ld.global.nc.v8.f32 {%0,%1,%2,%3,%4,%5,%6,%7}, [%8];"
        : "=f"(a.x), "=f"(a.y), "=f"(a.z), "=f"(a.w),
          "=f"(b.x), "=f"(b.y), "=f"(b.z), "=f"(b.w)
        : "l"(p));
}

__global__ void __launch_bounds__(NTHR)
casa_fused(const float* __restrict__ d, const float* __restrict__ y,
           int NE, int ngroups, float* __restrict__ out) {
    float a0 = 0.f, a1 = 0.f, a2 = 0.f, a3 = 0.f;
    const int stride = gridDim.x * blockDim.x;

    for (int g = blockIdx.x * blockDim.x + threadIdx.x; g < ngroups; g += stride) {
        const int base = g << 3;                   // 8 elements per group
        float4 dA, dB, yA, yB;
        ldg256(d + base, dA, dB);
        ldg256(y + base, yA, yB);
        const float d8 = __ldg(d + base + 8);
        const float y8 = __ldg(y + base + 8);

        term(a0, dA.x, dA.y, yA.x, yA.y);
        term(a1, dA.y, dA.z, yA.y, yA.z);
        term(a2, dA.z, dA.w, yA.z, yA.w);
        term(a3, dA.w, dB.x, yA.w, yB.x);
        term(a0, dB.x, dB.y, yB.x, yB.y);
        term(a1, dB.y, dB.z, yB.y, yB.z);
        term(a2, dB.z, dB.w, yB.z, yB.w);
        term(a3, dB.w, d8,   yB.w, y8);
    }

    float acc = (a0 + a1) + (a2 + a3);

    // block reduce (float)
    #pragma unroll
    for (int o = 16; o; o >>= 1) acc += __shfl_down_sync(0xffffffffu, acc, o);

    __shared__ float sh[NTHR / 32];
    __shared__ bool  s_last;
    const int lane = threadIdx.x & 31;
    const int w    = threadIdx.x >> 5;
    if (lane == 0) sh[w] = acc;
    __syncthreads();
    if (threadIdx.x == 0) {
        float v = 0.f;
        #pragma unroll
        for (int i = 0; i < NTHR / 32; i++) v += sh[i];
        g_partials[blockIdx.x] = v;
        __threadfence();
        unsigned t = atomicAdd(&g_ticket, 1u);
        s_last = (t == (unsigned)gridDim.x - 1u);
    }
    __syncthreads();
    if (!s_last) return;

    // ---- last block: deterministic double-precision finish ----
    const int tid = threadIdx.x;
    double v = 0.0;
    for (int i = tid; i < NBLK; i += NTHR)       // fixed-order per thread
        v += (double)g_partials[i];

    if (tid == 0) {
        for (int k = 8 * ngroups; k < NE; k++) { // tail (empty when NE%8==0)
            float t0 = d[k], t1 = d[k + 1], u0 = y[k], u1 = y[k + 1];
            float a = gex(u1 - u0) + gex(t1 - t0) - gex(t1 - u0) - gex(t0 - u1);
            v += 0.5 * (double)a - (double)gex(t0 - u0);
        }
        v += 0.5 * ((double)gex(d[0] - y[0]) - (double)gex(d[NE] - y[NE]));
        v += (double)NE;
    }

    #pragma unroll
    for (int o = 16; o; o >>= 1) v += __shfl_down_sync(0xffffffffu, v, o);

    __shared__ double shd[NTHR / 32];
    if (lane == 0) shd[w] = v;
    __syncthreads();
    if (tid == 0) {
        double t = 0.0;
        #pragma unroll
        for (int i = 0; i < NTHR / 32; i++) t += shd[i];
        out[0] = (float)t;
        g_ticket = 0;                  // reset for next graph replay
    }
}

extern "C" void kernel_launch(void* const* d_in, const int* in_sizes, int n_in,
                              void* d_out, int out_size) {
    const float* d = (const float*)d_in[0];
    const float* y = (const float*)d_in[1];
    float* out = (float*)d_out;

    const int n  = in_sizes[0];
    const int NE = n - 2;               // 4,000,000 for N = 4,000,002
    const int ngroups = NE / 8;         // 8 consecutive k per group

    casa_fused<<<NBLK, NTHR>>>(d, y, NE, ngroups, out);
}